// round 7
// baseline (speedup 1.0000x reference)
#include <cuda_runtime.h>
#include <cstdint>

#define NB      32768
#define DIN     784
#define DH      512
#define DOUT    10
#define NSTEPS  25
#define BETA    0.9f
#define THR     1.0f

typedef unsigned long long u64;

// ---------------- static device scratch ----------------
__device__ float g_cur1[(size_t)NB * DH];

// ---------------- f32x2 helpers (sm_100+ family PTX) ----------------
__device__ __forceinline__ u64 pack2(float lo, float hi) {
    u64 r; asm("mov.b64 %0, {%1, %2};" : "=l"(r) : "f"(lo), "f"(hi)); return r;
}
__device__ __forceinline__ void unpack2(u64 v, float& lo, float& hi) {
    asm("mov.b64 {%0, %1}, %2;" : "=f"(lo), "=f"(hi) : "l"(v));
}
__device__ __forceinline__ u64 fma2(u64 a, u64 b, u64 c) {
    u64 d; asm("fma.rn.f32x2 %0, %1, %2, %3;" : "=l"(d) : "l"(a), "l"(b), "l"(c)); return d;
}
__device__ __forceinline__ u64 add2(u64 a, u64 b) {
    u64 d; asm("add.rn.f32x2 %0, %1, %2;" : "=l"(d) : "l"(a), "l"(b)); return d;
}

// ---------------------------------------------------------------------------
// GEMM via packed f32x2 FFMA (R6 version, measured ~507us, per-half IEEE RN).
// CTA 128x256, 256 thr, micro-tile 8x16, k-tile 16, double-buffered smem.
// ---------------------------------------------------------------------------
#define BM 128
#define BN 256
#define BK 16
#define GNKT (DIN / BK)       // 49
#define ARS 132
#define BRS 260
#define SMEM_GEMM ((2 * BK * ARS + 2 * BK * BRS) * 4)   // 50176 B

__global__ void __launch_bounds__(256, 1)
gemm1_f32x2(const float* __restrict__ X,
            const float* __restrict__ W1,
            const float* __restrict__ b1)
{
    extern __shared__ float sm[];
    float (*As)[BK][ARS] = (float (*)[BK][ARS])sm;
    float (*Bs)[BK][BRS] = (float (*)[BK][BRS])(sm + 2 * BK * ARS);

    const int tid = threadIdx.x;
    const int bm = blockIdx.y * BM;
    const int bn = blockIdx.x * BN;
    const int ty = tid >> 4;
    const int tx = tid & 15;

    const int lmA = tid >> 1, lkA = (tid & 1) * 8;
    const int lmB = tid;
    const float* aptr = X  + (size_t)(bm + lmA) * DIN + lkA;
    const float* bptr = W1 + (size_t)(bn + lmB) * DIN;

    float4 fa0, fa1, fb0, fb1, fb2, fb3;
    fa0 = *(const float4*)(aptr);
    fa1 = *(const float4*)(aptr + 4);
    fb0 = *(const float4*)(bptr);
    fb1 = *(const float4*)(bptr + 4);
    fb2 = *(const float4*)(bptr + 8);
    fb3 = *(const float4*)(bptr + 12);
    #pragma unroll
    for (int q = 0; q < 4; q++) {
        As[0][lkA + q][lmA]     = ((const float*)&fa0)[q];
        As[0][lkA + 4 + q][lmA] = ((const float*)&fa1)[q];
        Bs[0][q][lmB]      = ((const float*)&fb0)[q];
        Bs[0][4 + q][lmB]  = ((const float*)&fb1)[q];
        Bs[0][8 + q][lmB]  = ((const float*)&fb2)[q];
        Bs[0][12 + q][lmB] = ((const float*)&fb3)[q];
    }
    __syncthreads();

    u64 acc[8][8];
    #pragma unroll
    for (int i = 0; i < 8; i++)
        #pragma unroll
        for (int p = 0; p < 8; p++) acc[i][p] = 0ULL;

    for (int kt = 0; kt < GNKT; kt++) {
        const int buf = kt & 1;
        if (kt + 1 < GNKT) {
            const float* ap = aptr + (kt + 1) * BK;
            const float* bp = bptr + (kt + 1) * BK;
            fa0 = *(const float4*)(ap);
            fa1 = *(const float4*)(ap + 4);
            fb0 = *(const float4*)(bp);
            fb1 = *(const float4*)(bp + 4);
            fb2 = *(const float4*)(bp + 8);
            fb3 = *(const float4*)(bp + 12);
        }
        #pragma unroll
        for (int k = 0; k < BK; k++) {
            const float4 av0 = *(const float4*)(&As[buf][k][ty * 4]);
            const float4 av1 = *(const float4*)(&As[buf][k][ty * 4 + 64]);
            u64 b2v[8];
            #pragma unroll
            for (int c = 0; c < 4; c++) {
                const ulonglong2 bv = *(const ulonglong2*)(&Bs[buf][k][tx * 4 + c * 64]);
                b2v[c * 2]     = bv.x;
                b2v[c * 2 + 1] = bv.y;
            }
            const float a[8] = {av0.x, av0.y, av0.z, av0.w, av1.x, av1.y, av1.z, av1.w};
            #pragma unroll
            for (int i = 0; i < 8; i++) {
                const u64 a2 = pack2(a[i], a[i]);
                #pragma unroll
                for (int p = 0; p < 8; p++)
                    acc[i][p] = fma2(a2, b2v[p], acc[i][p]);
            }
        }
        if (kt + 1 < GNKT) {
            const int nb = buf ^ 1;
            #pragma unroll
            for (int q = 0; q < 4; q++) {
                As[nb][lkA + q][lmA]     = ((const float*)&fa0)[q];
                As[nb][lkA + 4 + q][lmA] = ((const float*)&fa1)[q];
                Bs[nb][q][lmB]      = ((const float*)&fb0)[q];
                Bs[nb][4 + q][lmB]  = ((const float*)&fb1)[q];
                Bs[nb][8 + q][lmB]  = ((const float*)&fb2)[q];
                Bs[nb][12 + q][lmB] = ((const float*)&fb3)[q];
            }
        }
        __syncthreads();
    }

    float4 bias[4];
    #pragma unroll
    for (int c = 0; c < 4; c++)
        bias[c] = __ldg((const float4*)(b1 + bn + tx * 4 + c * 64));

    #pragma unroll
    for (int i = 0; i < 8; i++) {
        const int m = bm + ty * 4 + (i >> 2) * 64 + (i & 3);
        float* orow = g_cur1 + (size_t)m * DH + bn + tx * 4;
        #pragma unroll
        for (int c = 0; c < 4; c++) {
            float v0, v1, v2, v3;
            unpack2(acc[i][c * 2],     v0, v1);
            unpack2(acc[i][c * 2 + 1], v2, v3);
            float4 v = {v0 + bias[c].x, v1 + bias[c].y, v2 + bias[c].z, v3 + bias[c].w};
            *(float4*)(orow + c * 64) = v;
        }
    }
}

// ---------------------------------------------------------------------------
// Fused 25-step SNN. One warp = 2 rows. SCALAR LIF state (low regs, R2-style);
// only the spike is packed: fma2(spk01, (w,w), part) == R2's predicated FADD
// bit-for-bit (spk in {0,1}: 1*w exact, +0 exact). W2 stored [n][j] as packed
// (w,w) u64: 80B rows -> lane word-stride 20 -> conflict-free LDS.128, and 10
// weights come in 5 LDS.128 instead of 10 LDS.32. Same sum order as R2.
// ---------------------------------------------------------------------------
__global__ __launch_bounds__(256, 2)
void snn_kernel(const float* __restrict__ W2,
                const float* __restrict__ b2,
                float* __restrict__ out)
{
    __shared__ __align__(16) u64 w2d[DH][DOUT];   // 40 KB, [n][j] = (w,w)
    for (int idx = threadIdx.x; idx < DOUT * DH; idx += 256) {
        const int j = idx / DH, n = idx % DH;
        const float w = W2[idx];
        w2d[n][j] = pack2(w, w);
    }
    __syncthreads();

    const int warp = threadIdx.x >> 5;
    const int lane = threadIdx.x & 31;
    const int row0 = (blockIdx.x * 8 + warp) * 2;
    const int row1 = row0 + 1;

    float cur1a[16], cur1b[16], mem1a[16], mem1b[16];
    const float* ca = g_cur1 + (size_t)row0 * DH + lane;
    const float* cb = g_cur1 + (size_t)row1 * DH + lane;
    #pragma unroll
    for (int i = 0; i < 16; i++) {
        cur1a[i] = ca[i * 32];
        cur1b[i] = cb[i * 32];
        mem1a[i] = 0.f;
        mem1b[i] = 0.f;
    }

    float mem2a = 0.f, mem2b = 0.f;
    const float b2v = (lane < DOUT) ? b2[lane] : 0.f;
    const size_t MEMOFF = (size_t)NSTEPS * NB * DOUT;

    for (int t = 0; t < NSTEPS; t++) {
        u64 part[DOUT];
        #pragma unroll
        for (int j = 0; j < DOUT; j++) part[j] = 0ULL;

        #pragma unroll
        for (int i = 0; i < 16; i++) {
            // layer-1 LIF, scalar (identical expressions to R2)
            float ma = mem1a[i];
            ma = BETA * ma + cur1a[i] - ((ma > THR) ? THR : 0.f);
            mem1a[i] = ma;
            float mb = mem1b[i];
            mb = BETA * mb + cur1b[i] - ((mb > THR) ? THR : 0.f);
            mem1b[i] = mb;

            // packed 0/1 spike multiplier for both rows
            const u64 spk = pack2((ma > THR) ? 1.f : 0.f, (mb > THR) ? 1.f : 0.f);

            const int n = i * 32 + lane;
            const ulonglong2* wp = (const ulonglong2*)&w2d[n][0];
            #pragma unroll
            for (int c = 0; c < 5; c++) {
                const ulonglong2 W = wp[c];                  // LDS.128: j=2c, 2c+1
                part[2 * c]     = fma2(spk, W.x, part[2 * c]);
                part[2 * c + 1] = fma2(spk, W.y, part[2 * c + 1]);
            }
        }

        // butterfly reduce (same per-half combine order as R2)
        #pragma unroll
        for (int off = 16; off > 0; off >>= 1)
            #pragma unroll
            for (int j = 0; j < DOUT; j++)
                part[j] = add2(part[j], __shfl_xor_sync(0xffffffffu, part[j], off));

        if (lane < DOUT) {
            float pa, pb;
            unpack2(part[lane], pa, pb);
            const float c2a = pa + b2v;
            const float c2b = pb + b2v;
            const float na = BETA * mem2a + c2a - ((mem2a > THR) ? THR : 0.f);
            const float nb = BETA * mem2b + c2b - ((mem2b > THR) ? THR : 0.f);
            mem2a = na;
            mem2b = nb;
            const float ska = (na > THR) ? 1.f : 0.f;
            const float skb = (nb > THR) ? 1.f : 0.f;

            const size_t base = (size_t)t * NB * DOUT;
            out[base + (size_t)row0 * DOUT + lane]          = ska;
            out[base + (size_t)row1 * DOUT + lane]          = skb;
            out[MEMOFF + base + (size_t)row0 * DOUT + lane] = na;
            out[MEMOFF + base + (size_t)row1 * DOUT + lane] = nb;
        }
    }
}

// ---------------------------------------------------------------------------
extern "C" void kernel_launch(void* const* d_in, const int* in_sizes, int n_in,
                              void* d_out, int out_size)
{
    (void)in_sizes; (void)n_in; (void)out_size;
    const float* x  = (const float*)d_in[0];   // [32768, 784]
    const float* W1 = (const float*)d_in[1];   // [512, 784]
    const float* b1 = (const float*)d_in[2];   // [512]
    const float* W2 = (const float*)d_in[3];   // [10, 512]
    const float* b2 = (const float*)d_in[4];   // [10]
    float* out = (float*)d_out;                // [2, 25, 32768, 10]

    cudaFuncSetAttribute(gemm1_f32x2, cudaFuncAttributeMaxDynamicSharedMemorySize, SMEM_GEMM);
    dim3 ggrid(DH / BN, NB / BM);              // (2, 256)
    gemm1_f32x2<<<ggrid, 256, SMEM_GEMM>>>(x, W1, b1);

    snn_kernel<<<NB / 16, 256>>>(W2, b2, out); // 8 warps x 2 rows
}

// round 8
// speedup vs baseline: 1.2057x; 1.2057x over previous
#include <cuda_runtime.h>
#include <cstdint>

#define NB      32768
#define DIN     784
#define DH      512
#define DOUT    10
#define NSTEPS  25
#define BETA    0.9f
#define THR     1.0f

typedef unsigned long long u64;

// ---------------- static device scratch ----------------
__device__ float g_cur1[(size_t)NB * DH];

// ---------------- f32x2 helpers (sm_100+ family PTX) ----------------
__device__ __forceinline__ u64 pack2(float lo, float hi) {
    u64 r; asm("mov.b64 %0, {%1, %2};" : "=l"(r) : "f"(lo), "f"(hi)); return r;
}
__device__ __forceinline__ void unpack2(u64 v, float& lo, float& hi) {
    asm("mov.b64 {%0, %1}, %2;" : "=f"(lo), "=f"(hi) : "l"(v));
}
__device__ __forceinline__ u64 fma2(u64 a, u64 b, u64 c) {
    u64 d; asm("fma.rn.f32x2 %0, %1, %2, %3;" : "=l"(d) : "l"(a), "l"(b), "l"(c)); return d;
}
__device__ __forceinline__ u64 add2(u64 a, u64 b) {
    u64 d; asm("add.rn.f32x2 %0, %1, %2;" : "=l"(d) : "l"(a), "l"(b)); return d;
}

// ---------------------------------------------------------------------------
// GEMM via packed f32x2 FFMA (R6 version, measured ~507us, per-half IEEE RN).
// CTA 128x256, 256 thr, micro-tile 8x16, k-tile 16, double-buffered smem.
// ---------------------------------------------------------------------------
#define BM 128
#define BN 256
#define BK 16
#define GNKT (DIN / BK)       // 49
#define ARS 132
#define BRS 260
#define SMEM_GEMM ((2 * BK * ARS + 2 * BK * BRS) * 4)   // 50176 B

__global__ void __launch_bounds__(256, 1)
gemm1_f32x2(const float* __restrict__ X,
            const float* __restrict__ W1,
            const float* __restrict__ b1)
{
    extern __shared__ float sm[];
    float (*As)[BK][ARS] = (float (*)[BK][ARS])sm;
    float (*Bs)[BK][BRS] = (float (*)[BK][BRS])(sm + 2 * BK * ARS);

    const int tid = threadIdx.x;
    const int bm = blockIdx.y * BM;
    const int bn = blockIdx.x * BN;
    const int ty = tid >> 4;
    const int tx = tid & 15;

    const int lmA = tid >> 1, lkA = (tid & 1) * 8;
    const int lmB = tid;
    const float* aptr = X  + (size_t)(bm + lmA) * DIN + lkA;
    const float* bptr = W1 + (size_t)(bn + lmB) * DIN;

    float4 fa0, fa1, fb0, fb1, fb2, fb3;
    fa0 = *(const float4*)(aptr);
    fa1 = *(const float4*)(aptr + 4);
    fb0 = *(const float4*)(bptr);
    fb1 = *(const float4*)(bptr + 4);
    fb2 = *(const float4*)(bptr + 8);
    fb3 = *(const float4*)(bptr + 12);
    #pragma unroll
    for (int q = 0; q < 4; q++) {
        As[0][lkA + q][lmA]     = ((const float*)&fa0)[q];
        As[0][lkA + 4 + q][lmA] = ((const float*)&fa1)[q];
        Bs[0][q][lmB]      = ((const float*)&fb0)[q];
        Bs[0][4 + q][lmB]  = ((const float*)&fb1)[q];
        Bs[0][8 + q][lmB]  = ((const float*)&fb2)[q];
        Bs[0][12 + q][lmB] = ((const float*)&fb3)[q];
    }
    __syncthreads();

    u64 acc[8][8];
    #pragma unroll
    for (int i = 0; i < 8; i++)
        #pragma unroll
        for (int p = 0; p < 8; p++) acc[i][p] = 0ULL;

    for (int kt = 0; kt < GNKT; kt++) {
        const int buf = kt & 1;
        if (kt + 1 < GNKT) {
            const float* ap = aptr + (kt + 1) * BK;
            const float* bp = bptr + (kt + 1) * BK;
            fa0 = *(const float4*)(ap);
            fa1 = *(const float4*)(ap + 4);
            fb0 = *(const float4*)(bp);
            fb1 = *(const float4*)(bp + 4);
            fb2 = *(const float4*)(bp + 8);
            fb3 = *(const float4*)(bp + 12);
        }
        #pragma unroll
        for (int k = 0; k < BK; k++) {
            const float4 av0 = *(const float4*)(&As[buf][k][ty * 4]);
            const float4 av1 = *(const float4*)(&As[buf][k][ty * 4 + 64]);
            u64 b2v[8];
            #pragma unroll
            for (int c = 0; c < 4; c++) {
                const ulonglong2 bv = *(const ulonglong2*)(&Bs[buf][k][tx * 4 + c * 64]);
                b2v[c * 2]     = bv.x;
                b2v[c * 2 + 1] = bv.y;
            }
            const float a[8] = {av0.x, av0.y, av0.z, av0.w, av1.x, av1.y, av1.z, av1.w};
            #pragma unroll
            for (int i = 0; i < 8; i++) {
                const u64 a2 = pack2(a[i], a[i]);
                #pragma unroll
                for (int p = 0; p < 8; p++)
                    acc[i][p] = fma2(a2, b2v[p], acc[i][p]);
            }
        }
        if (kt + 1 < GNKT) {
            const int nb = buf ^ 1;
            #pragma unroll
            for (int q = 0; q < 4; q++) {
                As[nb][lkA + q][lmA]     = ((const float*)&fa0)[q];
                As[nb][lkA + 4 + q][lmA] = ((const float*)&fa1)[q];
                Bs[nb][q][lmB]      = ((const float*)&fb0)[q];
                Bs[nb][4 + q][lmB]  = ((const float*)&fb1)[q];
                Bs[nb][8 + q][lmB]  = ((const float*)&fb2)[q];
                Bs[nb][12 + q][lmB] = ((const float*)&fb3)[q];
            }
        }
        __syncthreads();
    }

    float4 bias[4];
    #pragma unroll
    for (int c = 0; c < 4; c++)
        bias[c] = __ldg((const float4*)(b1 + bn + tx * 4 + c * 64));

    #pragma unroll
    for (int i = 0; i < 8; i++) {
        const int m = bm + ty * 4 + (i >> 2) * 64 + (i & 3);
        float* orow = g_cur1 + (size_t)m * DH + bn + tx * 4;
        #pragma unroll
        for (int c = 0; c < 4; c++) {
            float v0, v1, v2, v3;
            unpack2(acc[i][c * 2],     v0, v1);
            unpack2(acc[i][c * 2 + 1], v2, v3);
            float4 v = {v0 + bias[c].x, v1 + bias[c].y, v2 + bias[c].z, v3 + bias[c].w};
            *(float4*)(orow + c * 64) = v;
        }
    }
}

// ---------------------------------------------------------------------------
// Fused 25-step SNN. One warp = 2 rows, scalar LIF state.
// W2 transposed SCALAR in smem: w2t[n][12] (48B padded rows, word-stride 12
// -> conflict-free LDS.128/LDS.64, 40B/lane/i == R2 bytes, 3 instrs not 10).
// The 16B loads natively give (w_2c, w_2c+1) u64 pairs; spike is duplicated
// (sa,sa) once per row per i. fma2((sa,sa),(wj,wj1),part) per half ==
// R2's predicated FADD bit-for-bit (sa in {0,1}). Same sum order as R2.
// ---------------------------------------------------------------------------
#define WTS 12   // padded row stride (floats)

__global__ __launch_bounds__(256, 2)
void snn_kernel(const float* __restrict__ W2,
                const float* __restrict__ b2,
                float* __restrict__ out)
{
    __shared__ __align__(16) float w2t[DH][WTS];   // 24 KB
    for (int idx = threadIdx.x; idx < DOUT * DH; idx += 256) {
        const int j = idx / DH, n = idx % DH;      // W2 row-major [j][n]
        w2t[n][j] = W2[idx];
    }
    __syncthreads();

    const int warp = threadIdx.x >> 5;
    const int lane = threadIdx.x & 31;
    const int row0 = (blockIdx.x * 8 + warp) * 2;
    const int row1 = row0 + 1;

    float cur1a[16], cur1b[16], mem1a[16], mem1b[16];
    const float* ca = g_cur1 + (size_t)row0 * DH + lane;
    const float* cb = g_cur1 + (size_t)row1 * DH + lane;
    #pragma unroll
    for (int i = 0; i < 16; i++) {
        cur1a[i] = ca[i * 32];
        cur1b[i] = cb[i * 32];
        mem1a[i] = 0.f;
        mem1b[i] = 0.f;
    }

    float mem2a = 0.f, mem2b = 0.f;
    const float b2v = (lane < DOUT) ? b2[lane] : 0.f;
    const size_t MEMOFF = (size_t)NSTEPS * NB * DOUT;

    for (int t = 0; t < NSTEPS; t++) {
        u64 pA[5], pB[5];   // pX[c] = (sum_j=2c, sum_j=2c+1) for row a / b
        #pragma unroll
        for (int c = 0; c < 5; c++) { pA[c] = 0ULL; pB[c] = 0ULL; }

        #pragma unroll
        for (int i = 0; i < 16; i++) {
            // layer-1 LIF, scalar (identical expressions to R2)
            float ma = mem1a[i];
            ma = BETA * ma + cur1a[i] - ((ma > THR) ? THR : 0.f);
            mem1a[i] = ma;
            float mb = mem1b[i];
            mb = BETA * mb + cur1b[i] - ((mb > THR) ? THR : 0.f);
            mem1b[i] = mb;

            const float sa = (ma > THR) ? 1.f : 0.f;
            const float sb = (mb > THR) ? 1.f : 0.f;
            const u64 sa2 = pack2(sa, sa);
            const u64 sb2 = pack2(sb, sb);

            // 40B of weights: 2x LDS.128 + 1x LDS.64, conflict-free
            const float* wr = &w2t[i * 32 + lane][0];
            const ulonglong2 w01 = *(const ulonglong2*)(wr);      // (w0,w1),(w2,w3)
            const ulonglong2 w23 = *(const ulonglong2*)(wr + 4);  // (w4,w5),(w6,w7)
            const u64        w4  = *(const u64*)(wr + 8);         // (w8,w9)

            pA[0] = fma2(sa2, w01.x, pA[0]);
            pA[1] = fma2(sa2, w01.y, pA[1]);
            pA[2] = fma2(sa2, w23.x, pA[2]);
            pA[3] = fma2(sa2, w23.y, pA[3]);
            pA[4] = fma2(sa2, w4,    pA[4]);
            pB[0] = fma2(sb2, w01.x, pB[0]);
            pB[1] = fma2(sb2, w01.y, pB[1]);
            pB[2] = fma2(sb2, w23.x, pB[2]);
            pB[3] = fma2(sb2, w23.y, pB[3]);
            pB[4] = fma2(sb2, w4,    pB[4]);
        }

        // butterfly reduce (per-half combine order identical to R2)
        #pragma unroll
        for (int off = 16; off > 0; off >>= 1)
            #pragma unroll
            for (int c = 0; c < 5; c++) {
                pA[c] = add2(pA[c], __shfl_xor_sync(0xffffffffu, pA[c], off));
                pB[c] = add2(pB[c], __shfl_xor_sync(0xffffffffu, pB[c], off));
            }

        if (lane < DOUT) {
            // constant select chain (no dynamic register indexing -> no spills)
            const int h = lane >> 1;
            const u64 vA = (h == 0) ? pA[0] : (h == 1) ? pA[1] : (h == 2) ? pA[2]
                         : (h == 3) ? pA[3] : pA[4];
            const u64 vB = (h == 0) ? pB[0] : (h == 1) ? pB[1] : (h == 2) ? pB[2]
                         : (h == 3) ? pB[3] : pB[4];
            float aLo, aHi, bLo, bHi;
            unpack2(vA, aLo, aHi);
            unpack2(vB, bLo, bHi);
            const float pa = (lane & 1) ? aHi : aLo;
            const float pb = (lane & 1) ? bHi : bLo;

            const float c2a = pa + b2v;
            const float c2b = pb + b2v;
            const float na = BETA * mem2a + c2a - ((mem2a > THR) ? THR : 0.f);
            const float nb = BETA * mem2b + c2b - ((mem2b > THR) ? THR : 0.f);
            mem2a = na;
            mem2b = nb;
            const float ska = (na > THR) ? 1.f : 0.f;
            const float skb = (nb > THR) ? 1.f : 0.f;

            const size_t base = (size_t)t * NB * DOUT;
            out[base + (size_t)row0 * DOUT + lane]          = ska;
            out[base + (size_t)row1 * DOUT + lane]          = skb;
            out[MEMOFF + base + (size_t)row0 * DOUT + lane] = na;
            out[MEMOFF + base + (size_t)row1 * DOUT + lane] = nb;
        }
    }
}

// ---------------------------------------------------------------------------
extern "C" void kernel_launch(void* const* d_in, const int* in_sizes, int n_in,
                              void* d_out, int out_size)
{
    (void)in_sizes; (void)n_in; (void)out_size;
    const float* x  = (const float*)d_in[0];   // [32768, 784]
    const float* W1 = (const float*)d_in[1];   // [512, 784]
    const float* b1 = (const float*)d_in[2];   // [512]
    const float* W2 = (const float*)d_in[3];   // [10, 512]
    const float* b2 = (const float*)d_in[4];   // [10]
    float* out = (float*)d_out;                // [2, 25, 32768, 10]

    cudaFuncSetAttribute(gemm1_f32x2, cudaFuncAttributeMaxDynamicSharedMemorySize, SMEM_GEMM);
    dim3 ggrid(DH / BN, NB / BM);              // (2, 256)
    gemm1_f32x2<<<ggrid, 256, SMEM_GEMM>>>(x, W1, b1);

    snn_kernel<<<NB / 16, 256>>>(W2, b2, out); // 8 warps x 2 rows
}

// round 9
// speedup vs baseline: 1.3881x; 1.1513x over previous
#include <cuda_runtime.h>
#include <cstdint>

#define NB      32768
#define DIN     784
#define DH      512
#define DOUT    10
#define NSTEPS  25
#define BETA    0.9f
#define THR     1.0f
#define TB      5            // t-block size (25 = 5 x 5)
#define NTB     (NSTEPS / TB)

typedef unsigned long long u64;

// ---------------- static device scratch ----------------
__device__ float g_cur1[(size_t)NB * DH];

// ---------------- f32x2 helpers (sm_100+ family PTX) ----------------
__device__ __forceinline__ u64 pack2(float lo, float hi) {
    u64 r; asm("mov.b64 %0, {%1, %2};" : "=l"(r) : "f"(lo), "f"(hi)); return r;
}
__device__ __forceinline__ void unpack2(u64 v, float& lo, float& hi) {
    asm("mov.b64 {%0, %1}, %2;" : "=f"(lo), "=f"(hi) : "l"(v));
}
__device__ __forceinline__ u64 fma2(u64 a, u64 b, u64 c) {
    u64 d; asm("fma.rn.f32x2 %0, %1, %2, %3;" : "=l"(d) : "l"(a), "l"(b), "l"(c)); return d;
}
__device__ __forceinline__ u64 add2(u64 a, u64 b) {
    u64 d; asm("add.rn.f32x2 %0, %1, %2;" : "=l"(d) : "l"(a), "l"(b)); return d;
}

// ---------------------------------------------------------------------------
// GEMM via packed f32x2 FFMA (unchanged; ~80% of the 68TF/s f32x2 roofline).
// ---------------------------------------------------------------------------
#define BM 128
#define BN 256
#define BK 16
#define GNKT (DIN / BK)       // 49
#define ARS 132
#define BRS 260
#define SMEM_GEMM ((2 * BK * ARS + 2 * BK * BRS) * 4)   // 50176 B

__global__ void __launch_bounds__(256, 1)
gemm1_f32x2(const float* __restrict__ X,
            const float* __restrict__ W1,
            const float* __restrict__ b1)
{
    extern __shared__ float sm[];
    float (*As)[BK][ARS] = (float (*)[BK][ARS])sm;
    float (*Bs)[BK][BRS] = (float (*)[BK][BRS])(sm + 2 * BK * ARS);

    const int tid = threadIdx.x;
    const int bm = blockIdx.y * BM;
    const int bn = blockIdx.x * BN;
    const int ty = tid >> 4;
    const int tx = tid & 15;

    const int lmA = tid >> 1, lkA = (tid & 1) * 8;
    const int lmB = tid;
    const float* aptr = X  + (size_t)(bm + lmA) * DIN + lkA;
    const float* bptr = W1 + (size_t)(bn + lmB) * DIN;

    float4 fa0, fa1, fb0, fb1, fb2, fb3;
    fa0 = *(const float4*)(aptr);
    fa1 = *(const float4*)(aptr + 4);
    fb0 = *(const float4*)(bptr);
    fb1 = *(const float4*)(bptr + 4);
    fb2 = *(const float4*)(bptr + 8);
    fb3 = *(const float4*)(bptr + 12);
    #pragma unroll
    for (int q = 0; q < 4; q++) {
        As[0][lkA + q][lmA]     = ((const float*)&fa0)[q];
        As[0][lkA + 4 + q][lmA] = ((const float*)&fa1)[q];
        Bs[0][q][lmB]      = ((const float*)&fb0)[q];
        Bs[0][4 + q][lmB]  = ((const float*)&fb1)[q];
        Bs[0][8 + q][lmB]  = ((const float*)&fb2)[q];
        Bs[0][12 + q][lmB] = ((const float*)&fb3)[q];
    }
    __syncthreads();

    u64 acc[8][8];
    #pragma unroll
    for (int i = 0; i < 8; i++)
        #pragma unroll
        for (int p = 0; p < 8; p++) acc[i][p] = 0ULL;

    for (int kt = 0; kt < GNKT; kt++) {
        const int buf = kt & 1;
        if (kt + 1 < GNKT) {
            const float* ap = aptr + (kt + 1) * BK;
            const float* bp = bptr + (kt + 1) * BK;
            fa0 = *(const float4*)(ap);
            fa1 = *(const float4*)(ap + 4);
            fb0 = *(const float4*)(bp);
            fb1 = *(const float4*)(bp + 4);
            fb2 = *(const float4*)(bp + 8);
            fb3 = *(const float4*)(bp + 12);
        }
        #pragma unroll
        for (int k = 0; k < BK; k++) {
            const float4 av0 = *(const float4*)(&As[buf][k][ty * 4]);
            const float4 av1 = *(const float4*)(&As[buf][k][ty * 4 + 64]);
            u64 b2v[8];
            #pragma unroll
            for (int c = 0; c < 4; c++) {
                const ulonglong2 bv = *(const ulonglong2*)(&Bs[buf][k][tx * 4 + c * 64]);
                b2v[c * 2]     = bv.x;
                b2v[c * 2 + 1] = bv.y;
            }
            const float a[8] = {av0.x, av0.y, av0.z, av0.w, av1.x, av1.y, av1.z, av1.w};
            #pragma unroll
            for (int i = 0; i < 8; i++) {
                const u64 a2 = pack2(a[i], a[i]);
                #pragma unroll
                for (int p = 0; p < 8; p++)
                    acc[i][p] = fma2(a2, b2v[p], acc[i][p]);
            }
        }
        if (kt + 1 < GNKT) {
            const int nb = buf ^ 1;
            #pragma unroll
            for (int q = 0; q < 4; q++) {
                As[nb][lkA + q][lmA]     = ((const float*)&fa0)[q];
                As[nb][lkA + 4 + q][lmA] = ((const float*)&fa1)[q];
                Bs[nb][q][lmB]      = ((const float*)&fb0)[q];
                Bs[nb][4 + q][lmB]  = ((const float*)&fb1)[q];
                Bs[nb][8 + q][lmB]  = ((const float*)&fb2)[q];
                Bs[nb][12 + q][lmB] = ((const float*)&fb3)[q];
            }
        }
        __syncthreads();
    }

    float4 bias[4];
    #pragma unroll
    for (int c = 0; c < 4; c++)
        bias[c] = __ldg((const float4*)(b1 + bn + tx * 4 + c * 64));

    #pragma unroll
    for (int i = 0; i < 8; i++) {
        const int m = bm + ty * 4 + (i >> 2) * 64 + (i & 3);
        float* orow = g_cur1 + (size_t)m * DH + bn + tx * 4;
        #pragma unroll
        for (int c = 0; c < 4; c++) {
            float v0, v1, v2, v3;
            unpack2(acc[i][c * 2],     v0, v1);
            unpack2(acc[i][c * 2 + 1], v2, v3);
            float4 v = {v0 + bias[c].x, v1 + bias[c].y, v2 + bias[c].z, v3 + bias[c].w};
            *(float4*)(orow + c * 64) = v;
        }
    }
}

// ---------------------------------------------------------------------------
// Fused 25-step SNN, t-blocked. One warp = ONE row. Loop order: t-block outer,
// i (neuron group) middle, t-within-block inner -> each 40B weight read is
// reused across TB=5 timesteps (5x less smem crossbar than R8).
// Per-neuron LIF recurrence is t-sequential regardless of nesting; per-t
// accumulation still sums i=0..15 in order; fma2((s,s),(w2c,w2c+1)) per half
// == predicated FADD bit-for-bit. Numerics identical to R2/R8.
// ---------------------------------------------------------------------------
#define WTS 12   // padded W2^T row stride (floats): conflict-free, 16B-aligned

__global__ __launch_bounds__(256, 2)
void snn_kernel(const float* __restrict__ W2,
                const float* __restrict__ b2,
                float* __restrict__ out)
{
    __shared__ __align__(16) float w2t[DH][WTS];   // 24 KB
    for (int idx = threadIdx.x; idx < DOUT * DH; idx += 256) {
        const int j = idx / DH, n = idx % DH;      // W2 row-major [j][n]
        w2t[n][j] = W2[idx];
    }
    __syncthreads();

    const int warp = threadIdx.x >> 5;
    const int lane = threadIdx.x & 31;
    const int row  = blockIdx.x * 8 + warp;

    float cur1[16], mem1[16];
    const float* cr = g_cur1 + (size_t)row * DH + lane;
    #pragma unroll
    for (int i = 0; i < 16; i++) {
        cur1[i] = cr[i * 32];
        mem1[i] = 0.f;
    }

    float mem2 = 0.f;
    const float b2v = (lane < DOUT) ? b2[lane] : 0.f;
    const size_t MEMOFF = (size_t)NSTEPS * NB * DOUT;

    for (int tb = 0; tb < NTB; tb++) {
        // part[tt][c] = (sum_j=2c, sum_j=2c+1) at time tb*TB+tt
        u64 part[TB][5];
        #pragma unroll
        for (int tt = 0; tt < TB; tt++)
            #pragma unroll
            for (int c = 0; c < 5; c++) part[tt][c] = 0ULL;

        #pragma unroll
        for (int i = 0; i < 16; i++) {
            // weights for THIS lane's neuron, loaded once per t-block
            const float* wr = &w2t[i * 32 + lane][0];
            const ulonglong2 w01 = *(const ulonglong2*)(wr);      // (w0,w1),(w2,w3)
            const ulonglong2 w23 = *(const ulonglong2*)(wr + 4);  // (w4,w5),(w6,w7)
            const u64        w4  = *(const u64*)(wr + 8);         // (w8,w9)

            float m = mem1[i];
            const float c1 = cur1[i];
            #pragma unroll
            for (int tt = 0; tt < TB; tt++) {
                // LIF step (identical expression to R2)
                m = BETA * m + c1 - ((m > THR) ? THR : 0.f);
                const float s = (m > THR) ? 1.f : 0.f;
                const u64 s2 = pack2(s, s);
                part[tt][0] = fma2(s2, w01.x, part[tt][0]);
                part[tt][1] = fma2(s2, w01.y, part[tt][1]);
                part[tt][2] = fma2(s2, w23.x, part[tt][2]);
                part[tt][3] = fma2(s2, w23.y, part[tt][3]);
                part[tt][4] = fma2(s2, w4,    part[tt][4]);
            }
            mem1[i] = m;
        }

        // butterfly reduce all 25 u64 partials (same per-half order as R2)
        #pragma unroll
        for (int off = 16; off > 0; off >>= 1)
            #pragma unroll
            for (int tt = 0; tt < TB; tt++)
                #pragma unroll
                for (int c = 0; c < 5; c++)
                    part[tt][c] = add2(part[tt][c],
                                       __shfl_xor_sync(0xffffffffu, part[tt][c], off));

        if (lane < DOUT) {
            const int h = lane >> 1;
            #pragma unroll
            for (int tt = 0; tt < TB; tt++) {
                const u64 v = (h == 0) ? part[tt][0] : (h == 1) ? part[tt][1]
                            : (h == 2) ? part[tt][2] : (h == 3) ? part[tt][3]
                            : part[tt][4];
                float vLo, vHi;
                unpack2(v, vLo, vHi);
                const float p = (lane & 1) ? vHi : vLo;

                const float c2 = p + b2v;
                const float nm = BETA * mem2 + c2 - ((mem2 > THR) ? THR : 0.f);
                mem2 = nm;

                const int t = tb * TB + tt;
                const size_t base = (size_t)t * NB * DOUT + (size_t)row * DOUT + lane;
                out[base]          = (nm > THR) ? 1.f : 0.f;
                out[MEMOFF + base] = nm;
            }
        }
    }
}

// ---------------------------------------------------------------------------
extern "C" void kernel_launch(void* const* d_in, const int* in_sizes, int n_in,
                              void* d_out, int out_size)
{
    (void)in_sizes; (void)n_in; (void)out_size;
    const float* x  = (const float*)d_in[0];   // [32768, 784]
    const float* W1 = (const float*)d_in[1];   // [512, 784]
    const float* b1 = (const float*)d_in[2];   // [512]
    const float* W2 = (const float*)d_in[3];   // [10, 512]
    const float* b2 = (const float*)d_in[4];   // [10]
    float* out = (float*)d_out;                // [2, 25, 32768, 10]

    cudaFuncSetAttribute(gemm1_f32x2, cudaFuncAttributeMaxDynamicSharedMemorySize, SMEM_GEMM);
    dim3 ggrid(DH / BN, NB / BM);              // (2, 256)
    gemm1_f32x2<<<ggrid, 256, SMEM_GEMM>>>(x, W1, b1);

    snn_kernel<<<NB / 8, 256>>>(W2, b2, out);  // 8 warps x 1 row
}

// round 10
// speedup vs baseline: 1.4240x; 1.0259x over previous
#include <cuda_runtime.h>
#include <cstdint>

#define NB      32768
#define DIN     784
#define DH      512
#define DOUT    10
#define NSTEPS  25
#define BETA    0.9f
#define THR     1.0f
#define TB      5
#define NTB     (NSTEPS / TB)

typedef unsigned long long u64;

// ---------------- static device scratch ----------------
__device__ float g_cur1[(size_t)NB * DH];

// ---------------- f32x2 helpers (sm_100+ family PTX) ----------------
__device__ __forceinline__ u64 pack2(float lo, float hi) {
    u64 r; asm("mov.b64 %0, {%1, %2};" : "=l"(r) : "f"(lo), "f"(hi)); return r;
}
__device__ __forceinline__ void unpack2(u64 v, float& lo, float& hi) {
    asm("mov.b64 {%0, %1}, %2;" : "=f"(lo), "=f"(hi) : "l"(v));
}
__device__ __forceinline__ u64 fma2(u64 a, u64 b, u64 c) {
    u64 d; asm("fma.rn.f32x2 %0, %1, %2, %3;" : "=l"(d) : "l"(a), "l"(b), "l"(c)); return d;
}
__device__ __forceinline__ u64 add2(u64 a, u64 b) {
    u64 d; asm("add.rn.f32x2 %0, %1, %2;" : "=l"(d) : "l"(a), "l"(b)); return d;
}

// ---------------------------------------------------------------------------
// GEMM via packed f32x2 FFMA. A stored PRE-PACKED (a,a) as u64 in smem so the
// inner loop has zero pack movs (was 16 movs per k = 25% issue overhead).
// Same values, same FFMA2 op order as R6-R9 -> bit-identical output.
// ---------------------------------------------------------------------------
#define BM 128
#define BN 256
#define BK 16
#define GNKT (DIN / BK)       // 49
#define AR2 132               // A row stride in u64
#define BRS 260               // B row stride in floats
#define A_BYTES (2 * BK * AR2 * 8)          // 33792
#define SMEM_GEMM (A_BYTES + 2 * BK * BRS * 4)   // 67072

__global__ void __launch_bounds__(256, 1)
gemm1_f32x2(const float* __restrict__ X,
            const float* __restrict__ W1,
            const float* __restrict__ b1)
{
    extern __shared__ char smraw[];
    u64*   AsU = (u64*)smraw;                       // [2][BK][AR2] u64 (a,a)
    float* BsF = (float*)(smraw + A_BYTES);         // [2][BK][BRS] float

    const int tid = threadIdx.x;
    const int bm = blockIdx.y * BM;
    const int bn = blockIdx.x * BN;
    const int ty = tid >> 4;
    const int tx = tid & 15;

    const int lmA = tid >> 1, lkA = (tid & 1) * 8;
    const int lmB = tid;
    const float* aptr = X  + (size_t)(bm + lmA) * DIN + lkA;
    const float* bptr = W1 + (size_t)(bn + lmB) * DIN;

    float4 fa0, fa1, fb0, fb1, fb2, fb3;
    fa0 = *(const float4*)(aptr);
    fa1 = *(const float4*)(aptr + 4);
    fb0 = *(const float4*)(bptr);
    fb1 = *(const float4*)(bptr + 4);
    fb2 = *(const float4*)(bptr + 8);
    fb3 = *(const float4*)(bptr + 12);
    #pragma unroll
    for (int q = 0; q < 4; q++) {
        AsU[(lkA + q) * AR2 + lmA]     = pack2(((const float*)&fa0)[q], ((const float*)&fa0)[q]);
        AsU[(lkA + 4 + q) * AR2 + lmA] = pack2(((const float*)&fa1)[q], ((const float*)&fa1)[q]);
        BsF[q * BRS + lmB]        = ((const float*)&fb0)[q];
        BsF[(4 + q) * BRS + lmB]  = ((const float*)&fb1)[q];
        BsF[(8 + q) * BRS + lmB]  = ((const float*)&fb2)[q];
        BsF[(12 + q) * BRS + lmB] = ((const float*)&fb3)[q];
    }
    __syncthreads();

    u64 acc[8][8];
    #pragma unroll
    for (int i = 0; i < 8; i++)
        #pragma unroll
        for (int p = 0; p < 8; p++) acc[i][p] = 0ULL;

    for (int kt = 0; kt < GNKT; kt++) {
        const int buf = kt & 1;
        if (kt + 1 < GNKT) {
            const float* ap = aptr + (kt + 1) * BK;
            const float* bp = bptr + (kt + 1) * BK;
            fa0 = *(const float4*)(ap);
            fa1 = *(const float4*)(ap + 4);
            fb0 = *(const float4*)(bp);
            fb1 = *(const float4*)(bp + 4);
            fb2 = *(const float4*)(bp + 8);
            fb3 = *(const float4*)(bp + 12);
        }
        const u64*   Ab = AsU + buf * BK * AR2;
        const float* Bb = BsF + buf * BK * BRS;
        #pragma unroll
        for (int k = 0; k < BK; k++) {
            const u64* arow = Ab + k * AR2 + ty * 4;
            const ulonglong2 aA = *(const ulonglong2*)(arow);
            const ulonglong2 aB = *(const ulonglong2*)(arow + 2);
            const ulonglong2 aC = *(const ulonglong2*)(arow + 64);
            const ulonglong2 aD = *(const ulonglong2*)(arow + 66);
            const u64 a2v[8] = {aA.x, aA.y, aB.x, aB.y, aC.x, aC.y, aD.x, aD.y};
            u64 b2v[8];
            #pragma unroll
            for (int c = 0; c < 4; c++) {
                const ulonglong2 bv = *(const ulonglong2*)(&Bb[k * BRS + tx * 4 + c * 64]);
                b2v[c * 2]     = bv.x;
                b2v[c * 2 + 1] = bv.y;
            }
            #pragma unroll
            for (int i = 0; i < 8; i++)
                #pragma unroll
                for (int p = 0; p < 8; p++)
                    acc[i][p] = fma2(a2v[i], b2v[p], acc[i][p]);
        }
        if (kt + 1 < GNKT) {
            const int nb = buf ^ 1;
            u64*   An = AsU + nb * BK * AR2;
            float* Bn = BsF + nb * BK * BRS;
            #pragma unroll
            for (int q = 0; q < 4; q++) {
                An[(lkA + q) * AR2 + lmA]     = pack2(((const float*)&fa0)[q], ((const float*)&fa0)[q]);
                An[(lkA + 4 + q) * AR2 + lmA] = pack2(((const float*)&fa1)[q], ((const float*)&fa1)[q]);
                Bn[q * BRS + lmB]        = ((const float*)&fb0)[q];
                Bn[(4 + q) * BRS + lmB]  = ((const float*)&fb1)[q];
                Bn[(8 + q) * BRS + lmB]  = ((const float*)&fb2)[q];
                Bn[(12 + q) * BRS + lmB] = ((const float*)&fb3)[q];
            }
        }
        __syncthreads();
    }

    float4 bias[4];
    #pragma unroll
    for (int c = 0; c < 4; c++)
        bias[c] = __ldg((const float4*)(b1 + bn + tx * 4 + c * 64));

    #pragma unroll
    for (int i = 0; i < 8; i++) {
        const int m = bm + ty * 4 + (i >> 2) * 64 + (i & 3);
        float* orow = g_cur1 + (size_t)m * DH + bn + tx * 4;
        #pragma unroll
        for (int c = 0; c < 4; c++) {
            float v0, v1, v2, v3;
            unpack2(acc[i][c * 2],     v0, v1);
            unpack2(acc[i][c * 2 + 1], v2, v3);
            float4 v = {v0 + bias[c].x, v1 + bias[c].y, v2 + bias[c].z, v3 + bias[c].w};
            *(float4*)(orow + c * 64) = v;
        }
    }
}

// ---------------------------------------------------------------------------
// Fused 25-step SNN, t-blocked (R9 structure) with:
//  - tightened LIF: fma + predicated sub (t-0==t exactly), u64-select spike
//  - reduce-scatter reduction: same binary tree over lanes as the butterfly
//    (adds commutatively swapped only -> bit-identical), but each lane keeps
//    only the half matching its lane bit: ~40% fewer reduction instructions.
//    After 5 levels lane l holds fully-reduced value index l (= tt*5+c).
// ---------------------------------------------------------------------------
#define WTS 12
#define SPK1 0x3F8000003F800000ULL   // (1.0f, 1.0f)

__global__ __launch_bounds__(256, 2)
void snn_kernel(const float* __restrict__ W2,
                const float* __restrict__ b2,
                float* __restrict__ out)
{
    __shared__ __align__(16) float w2t[DH][WTS];   // 24 KB, W2 transposed
    for (int idx = threadIdx.x; idx < DOUT * DH; idx += 256) {
        const int j = idx / DH, n = idx % DH;
        w2t[n][j] = W2[idx];
    }
    __syncthreads();

    const int warp = threadIdx.x >> 5;
    const int lane = threadIdx.x & 31;
    const int row  = blockIdx.x * 8 + warp;

    float cur1[16], mem1[16];
    const float* cr = g_cur1 + (size_t)row * DH + lane;
    #pragma unroll
    for (int i = 0; i < 16; i++) {
        cur1[i] = cr[i * 32];
        mem1[i] = 0.f;
    }

    float mem2 = 0.f;
    const float b2v = (lane < DOUT) ? b2[lane] : 0.f;
    const size_t MEMOFF = (size_t)NSTEPS * NB * DOUT;
    const int cidx = (lane >> 1) > 4 ? 4 : (lane >> 1);   // consumer c index

    for (int tb = 0; tb < NTB; tb++) {
        u64 V[25];                 // V[tt*5+c] = (sum_j=2c, sum_j=2c+1) at tt
        #pragma unroll
        for (int v = 0; v < 25; v++) V[v] = 0ULL;

        #pragma unroll
        for (int i = 0; i < 16; i++) {
            const float* wr = &w2t[i * 32 + lane][0];
            const ulonglong2 w01 = *(const ulonglong2*)(wr);
            const ulonglong2 w23 = *(const ulonglong2*)(wr + 4);
            const u64        w4  = *(const u64*)(wr + 8);

            float m = mem1[i];
            const float c1 = cur1[i];
            #pragma unroll
            for (int tt = 0; tt < TB; tt++) {
                const bool p0 = m > THR;
                m = fmaf(BETA, m, c1);
                if (p0) m = m - THR;                       // t-0 == t: bit-identical
                const u64 s2 = (m > THR) ? SPK1 : 0ULL;    // packed (s,s), no movs
                V[tt * 5 + 0] = fma2(s2, w01.x, V[tt * 5 + 0]);
                V[tt * 5 + 1] = fma2(s2, w01.y, V[tt * 5 + 1]);
                V[tt * 5 + 2] = fma2(s2, w23.x, V[tt * 5 + 2]);
                V[tt * 5 + 3] = fma2(s2, w23.y, V[tt * 5 + 3]);
                V[tt * 5 + 4] = fma2(s2, w4,    V[tt * 5 + 4]);
            }
            mem1[i] = m;
        }

        // ---- reduce-scatter (same tree as butterfly -> bit-identical) ----
        // level 16: 32 conceptual slots (25 real) -> 16
        {
            const bool h = (lane & 16) != 0;
            #pragma unroll
            for (int s = 0; s < 16; s++) {
                const u64 lo = V[s];
                const u64 hi = (s + 16 < 25) ? V[s + 16] : 0ULL;
                const u64 snd  = h ? lo : hi;
                const u64 rcv  = __shfl_xor_sync(0xffffffffu, snd, 16);
                const u64 kept = h ? hi : lo;
                V[s] = add2(kept, rcv);
            }
        }
        {
            const bool h = (lane & 8) != 0;
            #pragma unroll
            for (int s = 0; s < 8; s++) {
                const u64 snd  = h ? V[s] : V[s + 8];
                const u64 rcv  = __shfl_xor_sync(0xffffffffu, snd, 8);
                const u64 kept = h ? V[s + 8] : V[s];
                V[s] = add2(kept, rcv);
            }
        }
        {
            const bool h = (lane & 4) != 0;
            #pragma unroll
            for (int s = 0; s < 4; s++) {
                const u64 snd  = h ? V[s] : V[s + 4];
                const u64 rcv  = __shfl_xor_sync(0xffffffffu, snd, 4);
                const u64 kept = h ? V[s + 4] : V[s];
                V[s] = add2(kept, rcv);
            }
        }
        {
            const bool h = (lane & 2) != 0;
            #pragma unroll
            for (int s = 0; s < 2; s++) {
                const u64 snd  = h ? V[s] : V[s + 2];
                const u64 rcv  = __shfl_xor_sync(0xffffffffu, snd, 2);
                const u64 kept = h ? V[s + 2] : V[s];
                V[s] = add2(kept, rcv);
            }
        }
        {
            const bool h = (lane & 1) != 0;
            const u64 snd  = h ? V[0] : V[1];
            const u64 rcv  = __shfl_xor_sync(0xffffffffu, snd, 1);
            const u64 kept = h ? V[1] : V[0];
            V[0] = add2(kept, rcv);       // lane l now holds value index l
        }

        // ---- gather + layer-2 LIF + stores ----
        #pragma unroll
        for (int tt = 0; tt < TB; tt++) {
            const u64 g = __shfl_sync(0xffffffffu, V[0], tt * 5 + cidx);
            if (lane < DOUT) {
                float gLo, gHi;
                unpack2(g, gLo, gHi);
                const float p = (lane & 1) ? gHi : gLo;

                const float c2 = p + b2v;
                const float nm = BETA * mem2 + c2 - ((mem2 > THR) ? THR : 0.f);
                mem2 = nm;

                const int t = tb * TB + tt;
                const size_t base = (size_t)t * NB * DOUT + (size_t)row * DOUT + lane;
                out[base]          = (nm > THR) ? 1.f : 0.f;
                out[MEMOFF + base] = nm;
            }
        }
    }
}

// ---------------------------------------------------------------------------
extern "C" void kernel_launch(void* const* d_in, const int* in_sizes, int n_in,
                              void* d_out, int out_size)
{
    (void)in_sizes; (void)n_in; (void)out_size;
    const float* x  = (const float*)d_in[0];   // [32768, 784]
    const float* W1 = (const float*)d_in[1];   // [512, 784]
    const float* b1 = (const float*)d_in[2];   // [512]
    const float* W2 = (const float*)d_in[3];   // [10, 512]
    const float* b2 = (const float*)d_in[4];   // [10]
    float* out = (float*)d_out;                // [2, 25, 32768, 10]

    cudaFuncSetAttribute(gemm1_f32x2, cudaFuncAttributeMaxDynamicSharedMemorySize, SMEM_GEMM);
    dim3 ggrid(DH / BN, NB / BM);              // (2, 256)
    gemm1_f32x2<<<ggrid, 256, SMEM_GEMM>>>(x, W1, b1);

    snn_kernel<<<NB / 8, 256>>>(W2, b2, out);  // 8 warps x 1 row
}